// round 12
// baseline (speedup 1.0000x reference)
#include <cuda_runtime.h>
#include <cuda.h>
#include <cstdint>

// Problem constants (reference: D=48, K=12, S=4, BS=8)
#define D_   48
#define N_   (D_ * D_)      // 2304
#define K_   12
#define KK_  (K_ * K_)      // 144
#define NW1_ 10
#define NW_  (NW1_ * NW1_)  // 100
#define BS_  8

#define CHUNK_IA     3
#define CHUNK_FLOATS (CHUNK_IA * K_ * KK_)   // 5184 floats
#define CHUNK_BYTES  (CHUNK_FLOATS * 4)      // 20736 B
#define HALF_FLOATS  (2 * CHUNK_FLOATS)      // 10368
#define WIN_FLOATS   (KK_ * KK_)             // 20736

// View x[b] as x4[pr][pc][qr][qc] (48^4). For window w=(wr,wc):
// out[b, w, (ia,ib), (ja,jb)] = x4[b][4wr+ia][4wc+ib][4wr+ja][4wc+jb].
// TMA box [qc=12, qr=12, pc=12, pr=3, b=1] at (4wc, 4wr, 4wc, 4wr+ia0, b)
// packs 3 consecutive ia-tiles densely in smem in exact output order.
//
// CTA = half window (6 ia) = 2 chunks, double-buffered:
//   issue both TMA loads up-front (2 mbarriers), then wait+bulk-store each.
// 41.5KB smem -> ~5 CTAs/SM resident; loads overlap stores chip-wide.

__global__ void __launch_bounds__(32) subm_tma_half(
    const __grid_constant__ CUtensorMap tmap, float* __restrict__ out)
{
    __shared__ alignas(128) float T[2][CHUNK_FLOATS];
    __shared__ alignas(8) unsigned long long mbar[2];

    if (threadIdx.x != 0) return;

    int blk = blockIdx.x;            // = (b*100 + w)*2 + h
    int h   = blk & 1;
    int bw  = blk >> 1;
    int w   = bw % NW_;
    int b   = bw / NW_;
    int wr  = w / NW1_;
    int wc  = w % NW1_;

    uint32_t s_t0, s_t1, s_m0, s_m1;
    asm("{ .reg .u64 t; cvta.to.shared.u64 t, %1; cvt.u32.u64 %0, t; }"
        : "=r"(s_t0) : "l"(T[0]));
    asm("{ .reg .u64 t; cvta.to.shared.u64 t, %1; cvt.u32.u64 %0, t; }"
        : "=r"(s_t1) : "l"(T[1]));
    asm("{ .reg .u64 t; cvta.to.shared.u64 t, %1; cvt.u32.u64 %0, t; }"
        : "=r"(s_m0) : "l"(&mbar[0]));
    asm("{ .reg .u64 t; cvta.to.shared.u64 t, %1; cvt.u32.u64 %0, t; }"
        : "=r"(s_m1) : "l"(&mbar[1]));

    asm volatile("mbarrier.init.shared.b64 [%0], 1;" :: "r"(s_m0) : "memory");
    asm volatile("mbarrier.init.shared.b64 [%0], 1;" :: "r"(s_m1) : "memory");
    asm volatile("fence.proxy.async.shared::cta;" ::: "memory");

    int qc0 = 4 * wc;
    int qr0 = 4 * wr;
    int pc0 = 4 * wc;
    int pr0 = 4 * wr + 6 * h;        // ia start for chunk 0; chunk 1 at +3

    // Issue both loads up-front
    asm volatile("mbarrier.arrive.expect_tx.shared.b64 _, [%0], %1;"
                 :: "r"(s_m0), "r"((uint32_t)CHUNK_BYTES) : "memory");
    asm volatile(
        "cp.async.bulk.tensor.5d.shared::cta.global.tile.mbarrier::complete_tx::bytes "
        "[%0], [%1, {%2, %3, %4, %5, %6}], [%7];"
        :: "r"(s_t0), "l"(&tmap),
           "r"(qc0), "r"(qr0), "r"(pc0), "r"(pr0), "r"(b), "r"(s_m0)
        : "memory");

    asm volatile("mbarrier.arrive.expect_tx.shared.b64 _, [%0], %1;"
                 :: "r"(s_m1), "r"((uint32_t)CHUNK_BYTES) : "memory");
    asm volatile(
        "cp.async.bulk.tensor.5d.shared::cta.global.tile.mbarrier::complete_tx::bytes "
        "[%0], [%1, {%2, %3, %4, %5, %6}], [%7];"
        :: "r"(s_t1), "l"(&tmap),
           "r"(qc0), "r"(qr0), "r"(pc0), "r"(pr0 + CHUNK_IA), "r"(b), "r"(s_m1)
        : "memory");

    float* dst = out + (size_t)bw * WIN_FLOATS + (size_t)h * HALF_FLOATS;

    // Drain chunk 0
    asm volatile(
        "{\n\t.reg .pred P1;\n\t"
        "LW0%=:\n\t"
        "mbarrier.try_wait.parity.shared.b64 P1, [%0], 0;\n\t"
        "@P1 bra LD0%=;\n\t"
        "bra LW0%=;\n\t"
        "LD0%=:\n\t}"
        :: "r"(s_m0) : "memory");
    asm volatile("cp.async.bulk.global.shared::cta.bulk_group [%0], [%1], %2;"
                 :: "l"(dst), "r"(s_t0), "r"((uint32_t)CHUNK_BYTES) : "memory");
    asm volatile("cp.async.bulk.commit_group;" ::: "memory");

    // Drain chunk 1
    asm volatile(
        "{\n\t.reg .pred P1;\n\t"
        "LW1%=:\n\t"
        "mbarrier.try_wait.parity.shared.b64 P1, [%0], 0;\n\t"
        "@P1 bra LD1%=;\n\t"
        "bra LW1%=;\n\t"
        "LD1%=:\n\t}"
        :: "r"(s_m1) : "memory");
    asm volatile("cp.async.bulk.global.shared::cta.bulk_group [%0], [%1], %2;"
                 :: "l"(dst + CHUNK_FLOATS), "r"(s_t1), "r"((uint32_t)CHUNK_BYTES)
                 : "memory");
    asm volatile("cp.async.bulk.commit_group;" ::: "memory");
    asm volatile("cp.async.bulk.wait_group 0;" ::: "memory");
}

// ---------------- fallback (plain gather, best known LDG design) ----------
__global__ void __launch_bounds__(256) submanifold_gather_q12(
    const float* __restrict__ x, float* __restrict__ out)
{
    int t = blockIdx.x * 256 + threadIdx.x;
    int q    = t % 36;
    int rest = t / 36;
    int ia   = rest % K_;
    rest     = rest / K_;
    int w    = rest % NW_;
    int b    = rest / NW_;
    int wr = w / NW1_;
    int wc = w % NW1_;
    int ja  = q / 3;
    int sub = q % 3;
    int r0 = (wr * 4 + ia) * D_ + wc * 4;
    int c  = (wr * 4 + ja) * D_ + wc * 4 + sub * 4;
    const float4* src = reinterpret_cast<const float4*>(x + ((size_t)b * N_ + r0) * N_ + c);
    size_t dbase = (((size_t)(b * NW_ + w)) * KK_ + ia * K_) * 36 + q;
    float4* dst = reinterpret_cast<float4*>(out) + dbase;
#pragma unroll
    for (int ib = 0; ib < K_; ib++)
        dst[(size_t)ib * 36] = src[(size_t)ib * (N_ / 4)];
}

// ---------------------------------------------------------------------------

typedef CUresult (*PFN_tmapEncode)(
    CUtensorMap*, CUtensorMapDataType, cuuint32_t, void*,
    const cuuint64_t*, const cuuint64_t*, const cuuint32_t*, const cuuint32_t*,
    CUtensorMapInterleave, CUtensorMapSwizzle, CUtensorMapL2promotion,
    CUtensorMapFloatOOBfill);

extern "C" void kernel_launch(void* const* d_in, const int* in_sizes, int n_in,
                              void* d_out, int out_size)
{
    float* x   = (float*)d_in[0];
    float* out = (float*)d_out;

    PFN_tmapEncode encode = nullptr;
    cudaDriverEntryPointQueryResult qres;
    cudaGetDriverEntryPoint("cuTensorMapEncodeTiled", (void**)&encode,
                            cudaEnableDefault, &qres);

    bool tma_ok = false;
    CUtensorMap tmap;
    if (encode && qres == cudaDriverEntryPointSuccess) {
        // 5D view of x: dims (innermost->outermost) [qc, qr, pc, pr, b]
        cuuint64_t dims[5]    = {48, 48, 48, 48, (cuuint64_t)BS_};
        cuuint64_t strides[4] = {
            48ull * 4,                    // qr : 192 B
            (cuuint64_t)N_ * 4,           // pc : 9216 B
            48ull * N_ * 4,               // pr : 442368 B
            (cuuint64_t)N_ * N_ * 4       // b  : 21233664 B
        };
        cuuint32_t box[5]  = {12, 12, 12, CHUNK_IA, 1};
        cuuint32_t estr[5] = {1, 1, 1, 1, 1};
        CUresult r = encode(&tmap, CU_TENSOR_MAP_DATA_TYPE_FLOAT32, 5, (void*)x,
                            dims, strides, box, estr,
                            CU_TENSOR_MAP_INTERLEAVE_NONE,
                            CU_TENSOR_MAP_SWIZZLE_NONE,
                            CU_TENSOR_MAP_L2_PROMOTION_L2_128B,
                            CU_TENSOR_MAP_FLOAT_OOB_FILL_NONE);
        tma_ok = (r == CUDA_SUCCESS);
    }

    if (tma_ok) {
        subm_tma_half<<<BS_ * NW_ * 2, 32>>>(tmap, out);   // 1600 CTAs
    } else {
        const int total_threads = BS_ * NW_ * K_ * 36;
        submanifold_gather_q12<<<total_threads / 256, 256>>>(x, out);
    }
}

// round 13
// speedup vs baseline: 1.3328x; 1.3328x over previous
#include <cuda_runtime.h>
#include <cuda.h>
#include <cstdint>

// Problem constants (reference: D=48, K=12, S=4, BS=8)
#define D_   48
#define N_   (D_ * D_)      // 2304
#define K_   12
#define KK_  (K_ * K_)      // 144
#define NW1_ 10
#define NW_  (NW1_ * NW1_)  // 100
#define BS_  8

#define TROWS 48
#define TCOLS 192
#define TILE_BYTES (TROWS * TCOLS * 4)   // 36864

// Tile keyed by SOURCE coords (b, pr, qrg):
//   rows pr*48 .. +48, cols qrg*192 .. +192 floats of x[b]  (dense, 768B rows)
// Each tile is loaded ONCE chip-wide (TMA), then serves every output chunk
// (wr = qrg - jB, ia = pr - 4wr, jB) with jB in 0..2 and window-validity:
//   out[b, wr*10+wc, ia*12+ib, 48jB + 12jaLoc + 4sub + e]
//     = T[4wc+ib][jaLoc*48 + 4wc + 4sub + e]
// This removes the cross-wr read duplication (L2 reads ~106MB -> ~65MB).

__global__ void __launch_bounds__(288) subm_tma_dedup(
    const __grid_constant__ CUtensorMap tmap, float* __restrict__ out)
{
    __shared__ alignas(128) float T[TROWS * TCOLS];
    __shared__ alignas(8) unsigned long long mbar;

    int bi   = blockIdx.x;          // = (b*48 + pr)*12 + qrg
    int qrg  = bi % 12;
    int pr   = (bi / 12) % 48;
    int b    = bi / (12 * 48);

    // validity: wr must satisfy 4wr <= pr <= 4wr+11  AND  qrg-2 <= wr <= qrg, 0<=wr<=9
    int wmin_row = pr - 11; wmin_row = wmin_row < 0 ? 0 : ((wmin_row + 3) >> 2);
    int wmax_row = pr >> 2; if (wmax_row > 9) wmax_row = 9;
    int wlo = qrg - 2; if (wlo < wmin_row) wlo = wmin_row; if (wlo < 0) wlo = 0;
    int whi = qrg;     if (whi > wmax_row) whi = wmax_row;
    if (wlo > whi) return;          // invalid tile, early exit

    uint32_t s_tile, s_mbar;
    asm("{ .reg .u64 t; cvta.to.shared.u64 t, %1; cvt.u32.u64 %0, t; }"
        : "=r"(s_tile) : "l"(T));
    asm("{ .reg .u64 t; cvta.to.shared.u64 t, %1; cvt.u32.u64 %0, t; }"
        : "=r"(s_mbar) : "l"(&mbar));

    if (threadIdx.x == 0) {
        asm volatile("mbarrier.init.shared.b64 [%0], 1;" :: "r"(s_mbar) : "memory");
        asm volatile("fence.proxy.async.shared::cta;" ::: "memory");
    }
    __syncthreads();

    if (threadIdx.x == 0) {
        asm volatile("mbarrier.arrive.expect_tx.shared.b64 _, [%0], %1;"
                     :: "r"(s_mbar), "r"((uint32_t)TILE_BYTES) : "memory");
        int c0 = qrg * TCOLS;       // element coord, inner dim
        int r0 = pr * D_;
        asm volatile(
            "cp.async.bulk.tensor.3d.shared::cta.global.tile.mbarrier::complete_tx::bytes "
            "[%0], [%1, {%2, %3, %4}], [%5];"
            :: "r"(s_tile), "l"(&tmap), "r"(c0), "r"(r0), "r"(b), "r"(s_mbar)
            : "memory");
    }

    // All threads wait for TMA completion (phase 0).
    asm volatile(
        "{\n\t.reg .pred P1;\n\t"
        "LW%=:\n\t"
        "mbarrier.try_wait.parity.shared.b64 P1, [%0], 0;\n\t"
        "@P1 bra LD%=;\n\t"
        "bra LW%=;\n\t"
        "LD%=:\n\t}"
        :: "r"(s_mbar) : "memory");

    // Phase 2: per-thread fixed (qj, ib, wcp); iterate wc (5 iters) per chunk.
    int tid  = threadIdx.x;
    int m    = tid % 144;
    int wcp  = tid / 144;           // 0 or 1
    int qj   = m % K_;
    int ib   = m / K_;
    int jaLoc = qj / 3;
    int sub   = qj % 3;

    int sidx0 = ib * TCOLS + jaLoc * 48 + sub * 4 + wcp * 772;

    for (int wr = wlo; wr <= whi; wr++) {
        int ia = pr - 4 * wr;
        int jB = qrg - wr;

        size_t obase = ((((size_t)b * NW_ + wr * NW1_) * KK_) + ia * K_ + ib) * KK_
                     + jB * 48 + qj * 4 + (size_t)wcp * (KK_ * KK_);
        int sidx = sidx0;
#pragma unroll
        for (int it = 0; it < 5; it++) {
            float4 v = *reinterpret_cast<const float4*>(&T[sidx]);
            __stcs(reinterpret_cast<float4*>(out + obase), v);
            sidx  += 2 * 772;
            obase += 2 * (size_t)(KK_ * KK_);
        }
    }
}

// ---------------- fallback (plain gather, best known LDG design) ----------
__global__ void __launch_bounds__(256) submanifold_gather_q12(
    const float* __restrict__ x, float* __restrict__ out)
{
    int t = blockIdx.x * 256 + threadIdx.x;
    int q    = t % 36;
    int rest = t / 36;
    int ia   = rest % K_;
    rest     = rest / K_;
    int w    = rest % NW_;
    int b    = rest / NW_;
    int wr = w / NW1_;
    int wc = w % NW1_;
    int ja  = q / 3;
    int sub = q % 3;
    int r0 = (wr * 4 + ia) * D_ + wc * 4;
    int c  = (wr * 4 + ja) * D_ + wc * 4 + sub * 4;
    const float4* src = reinterpret_cast<const float4*>(x + ((size_t)b * N_ + r0) * N_ + c);
    size_t dbase = (((size_t)(b * NW_ + w)) * KK_ + ia * K_) * 36 + q;
    float4* dst = reinterpret_cast<float4*>(out) + dbase;
#pragma unroll
    for (int ib = 0; ib < K_; ib++)
        dst[(size_t)ib * 36] = src[(size_t)ib * (N_ / 4)];
}

// ---------------------------------------------------------------------------

typedef CUresult (*PFN_tmapEncode)(
    CUtensorMap*, CUtensorMapDataType, cuuint32_t, void*,
    const cuuint64_t*, const cuuint64_t*, const cuuint32_t*, const cuuint32_t*,
    CUtensorMapInterleave, CUtensorMapSwizzle, CUtensorMapL2promotion,
    CUtensorMapFloatOOBfill);

extern "C" void kernel_launch(void* const* d_in, const int* in_sizes, int n_in,
                              void* d_out, int out_size)
{
    float* x   = (float*)d_in[0];
    float* out = (float*)d_out;

    PFN_tmapEncode encode = nullptr;
    cudaDriverEntryPointQueryResult qres;
    cudaGetDriverEntryPoint("cuTensorMapEncodeTiled", (void**)&encode,
                            cudaEnableDefault, &qres);

    bool tma_ok = false;
    CUtensorMap tmap;
    if (encode && qres == cudaDriverEntryPointSuccess) {
        // 3D view of x: [col (2304 floats, inner), row (2304), b (8)]
        cuuint64_t dims[3]    = {(cuuint64_t)N_, (cuuint64_t)N_, (cuuint64_t)BS_};
        cuuint64_t strides[2] = {
            (cuuint64_t)N_ * 4,            // row stride: 9216 B
            (cuuint64_t)N_ * N_ * 4        // batch stride
        };
        cuuint32_t box[3]  = {TCOLS, TROWS, 1};   // 192 x 48 x 1 (768B rows)
        cuuint32_t estr[3] = {1, 1, 1};
        CUresult r = encode(&tmap, CU_TENSOR_MAP_DATA_TYPE_FLOAT32, 3, (void*)x,
                            dims, strides, box, estr,
                            CU_TENSOR_MAP_INTERLEAVE_NONE,
                            CU_TENSOR_MAP_SWIZZLE_NONE,
                            CU_TENSOR_MAP_L2_PROMOTION_L2_128B,
                            CU_TENSOR_MAP_FLOAT_OOB_FILL_NONE);
        tma_ok = (r == CUDA_SUCCESS);
    }

    if (tma_ok) {
        subm_tma_dedup<<<BS_ * 48 * 12, 288>>>(tmap, out);   // 4608 CTAs (~38% valid)
    } else {
        const int total_threads = BS_ * NW_ * K_ * 36;
        submanifold_gather_q12<<<total_threads / 256, 256>>>(x, out);
    }
}